// round 10
// baseline (speedup 1.0000x reference)
#include <cuda_runtime.h>
#include <cstdint>
#include <math.h>

#define RANGE_MIN (-5.0f)
#define RANGE_MAX (5.0f)
#define MIN_BIN_SIZE 0.0001f
#define MIN_SLOPE 0.0001f
#define KBINS 8

// Per-block table build (thread 0). Writes:
//  tabA[b*4 + 0..3] = nxkw(-x_k*inv_w), inv_w, y_k, h   (16B stride, LDS.128-friendly)
//  tabB[b*2 + 0..1] = d_k, d_k1                          (8B stride, LDS.64-friendly)
//  kn[0..6] = interior knots x_pos[1..7]
__device__ __forceinline__ void build_table(const float* __restrict__ p,
                                            float* __restrict__ tabA,
                                            float* __restrict__ tabB,
                                            float* __restrict__ kn) {
    float w[KBINS], h[KBINS], d[KBINS + 1];
    float mw = -1e30f, mh = -1e30f;
    for (int i = 0; i < KBINS; i++) {
        mw = fmaxf(mw, p[i]);
        mh = fmaxf(mh, p[KBINS + i]);
    }
    float sw = 0.f, sh = 0.f;
    for (int i = 0; i < KBINS; i++) {
        w[i] = expf(p[i] - mw);         sw += w[i];
        h[i] = expf(p[KBINS + i] - mh); sh += h[i];
    }
    const float total = RANGE_MAX - RANGE_MIN;
    const float scale = total - KBINS * MIN_BIN_SIZE;
    for (int i = 0; i < KBINS; i++) {
        w[i] = w[i] / sw * scale + MIN_BIN_SIZE;
        h[i] = h[i] / sh * scale + MIN_BIN_SIZE;
    }
    const float off = logf(expf(1.0f - MIN_SLOPE) - 1.0f);
    for (int i = 0; i <= KBINS; i++) {
        float z = p[2 * KBINS + i] + off;
        d[i] = ((z > 20.f) ? z : log1pf(expf(z))) + MIN_SLOPE;
    }
    float xp[KBINS + 1], yp[KBINS + 1];
    xp[0] = RANGE_MIN; yp[0] = RANGE_MIN;
    float cx = 0.f, cy = 0.f;
    for (int i = 0; i < KBINS; i++) {
        cx += w[i]; xp[i + 1] = RANGE_MIN + cx;
        cy += h[i]; yp[i + 1] = RANGE_MIN + cy;
    }
    for (int b = 0; b < KBINS; b++) {
        float wid   = xp[b + 1] - xp[b];
        float hei   = yp[b + 1] - yp[b];
        float inv_w = 1.0f / wid;
        tabA[b * 4 + 0] = -xp[b] * inv_w;
        tabA[b * 4 + 1] = inv_w;
        tabA[b * 4 + 2] = yp[b];
        tabA[b * 4 + 3] = hei;
        tabB[b * 2 + 0] = d[b];
        tabB[b * 2 + 1] = d[b + 1];
    }
    for (int i = 0; i < 7; i++) kn[i] = xp[1 + i];
}

__device__ __forceinline__ void rqs_eval(float xx,
                                         const float* __restrict__ tabA,
                                         const float* __restrict__ tabB,
                                         float k1, float k2, float k3, float k4,
                                         float k5, float k6, float k7,
                                         float& y_out, float& ld_out) {
    float xc = fminf(fmaxf(xx, RANGE_MIN), RANGE_MAX);

    // binary searchsorted over 7 interior knots (side='right'); oA = bin*16 bytes
    bool  c2  = xc >= k4;
    float km1 = c2 ? k6 : k2;
    bool  c1  = xc >= km1;
    float kmA = c2 ? k7 : k3;
    float kmB = c2 ? k5 : k1;
    float km0 = c1 ? kmA : kmB;
    bool  c0  = xc >= km0;
    int oA = (c2 ? 64 : 0) + (c1 ? 32 : 0) + (c0 ? 16 : 0);
    int oB = oA >> 1;

    const float4 lo = *reinterpret_cast<const float4*>((const char*)tabA + oA); // nxkw, inv_w, y_k, h
    const float2 dd = *reinterpret_cast<const float2*>((const char*)tabB + oB); // d_k, d_k1

    float xi   = fmaf(xc, lo.y, lo.x);
    float omxi = 1.0f - xi;
    float xom  = xi * omxi;

    float dk = dd.x, dk1 = dd.y;
    float s  = lo.w * lo.y;                    // h * inv_w
    float cc = fmaf(-2.0f, s, dk + dk1);       // dk + dk1 - 2s

    float num = fmaf(s * xi, xi, dk * xom);
    float den = fmaf(cc, xom, s);
    float r   = __fdividef(1.0f, den);

    float y = fmaf(lo.w * num, r, lo.z);
    // tail: below range -> d0 (= dk of bin 0), above -> d8 (= dk1 of bin 7);
    // (xx - xc) == 0 in-range, so the select value is irrelevant there.
    float edge = (xx < 0.0f) ? dk : dk1;
    y = fmaf(xx - xc, edge, y);

    float t4    = fmaf(s + s, xom, (dk * omxi) * omxi);
    float inner = fmaf(dk1 * xi, xi, t4);
    float srr   = s * r;
    ld_out = __logf(srr * srr * inner);   // == log(edge slope) at clamped bounds
    y_out  = y;
}

// 4 LDG.128 up front (MLP=4); prep inlined per block (latency hidden behind
// the input loads and co-resident CTAs); 24B smem gather per element.
__global__ void __launch_bounds__(256, 5) rqs_main_kernel(
    const float* __restrict__ p,
    const float4* __restrict__ x4,
    float4* __restrict__ y4,
    float4* __restrict__ ld4
) {
    __shared__ __align__(16) float tabA[32];
    __shared__ __align__(8)  float tabB[16];
    __shared__               float kn[7];

    const int tid = threadIdx.x;
    const int i0  = blockIdx.x * 1024 + tid;

    // input loads first — independent of the table build
    float4 xv0 = __ldcs(&x4[i0]);
    float4 xv1 = __ldcs(&x4[i0 + 256]);
    float4 xv2 = __ldcs(&x4[i0 + 512]);
    float4 xv3 = __ldcs(&x4[i0 + 768]);

    if (tid == 0) build_table(p, tabA, tabB, kn);
    __syncthreads();

    const float k1 = kn[0], k2 = kn[1], k3 = kn[2], k4 = kn[3];
    const float k5 = kn[4], k6 = kn[5], k7 = kn[6];

    float4 yv, lv;

    rqs_eval(xv0.x, tabA, tabB, k1,k2,k3,k4,k5,k6,k7, yv.x, lv.x);
    rqs_eval(xv0.y, tabA, tabB, k1,k2,k3,k4,k5,k6,k7, yv.y, lv.y);
    rqs_eval(xv0.z, tabA, tabB, k1,k2,k3,k4,k5,k6,k7, yv.z, lv.z);
    rqs_eval(xv0.w, tabA, tabB, k1,k2,k3,k4,k5,k6,k7, yv.w, lv.w);
    __stcs(&y4[i0],  yv);
    __stcs(&ld4[i0], lv);

    rqs_eval(xv1.x, tabA, tabB, k1,k2,k3,k4,k5,k6,k7, yv.x, lv.x);
    rqs_eval(xv1.y, tabA, tabB, k1,k2,k3,k4,k5,k6,k7, yv.y, lv.y);
    rqs_eval(xv1.z, tabA, tabB, k1,k2,k3,k4,k5,k6,k7, yv.z, lv.z);
    rqs_eval(xv1.w, tabA, tabB, k1,k2,k3,k4,k5,k6,k7, yv.w, lv.w);
    __stcs(&y4[i0 + 256],  yv);
    __stcs(&ld4[i0 + 256], lv);

    rqs_eval(xv2.x, tabA, tabB, k1,k2,k3,k4,k5,k6,k7, yv.x, lv.x);
    rqs_eval(xv2.y, tabA, tabB, k1,k2,k3,k4,k5,k6,k7, yv.y, lv.y);
    rqs_eval(xv2.z, tabA, tabB, k1,k2,k3,k4,k5,k6,k7, yv.z, lv.z);
    rqs_eval(xv2.w, tabA, tabB, k1,k2,k3,k4,k5,k6,k7, yv.w, lv.w);
    __stcs(&y4[i0 + 512],  yv);
    __stcs(&ld4[i0 + 512], lv);

    rqs_eval(xv3.x, tabA, tabB, k1,k2,k3,k4,k5,k6,k7, yv.x, lv.x);
    rqs_eval(xv3.y, tabA, tabB, k1,k2,k3,k4,k5,k6,k7, yv.y, lv.y);
    rqs_eval(xv3.z, tabA, tabB, k1,k2,k3,k4,k5,k6,k7, yv.z, lv.z);
    rqs_eval(xv3.w, tabA, tabB, k1,k2,k3,k4,k5,k6,k7, yv.w, lv.w);
    __stcs(&y4[i0 + 768],  yv);
    __stcs(&ld4[i0 + 768], lv);
}

// Tail: handles [start, n) scalar-wise (not launched when n % 4096 == 0)
__global__ void rqs_tail_kernel(const float* __restrict__ p,
                                const float* __restrict__ x,
                                float* __restrict__ y,
                                float* __restrict__ ld,
                                int start, int n) {
    __shared__ __align__(16) float tabA[32];
    __shared__ __align__(8)  float tabB[16];
    __shared__               float kn[7];
    if (threadIdx.x == 0) build_table(p, tabA, tabB, kn);
    __syncthreads();
    for (int idx = start + blockIdx.x * blockDim.x + threadIdx.x; idx < n;
         idx += gridDim.x * blockDim.x) {
        float yy, ll;
        rqs_eval(x[idx], tabA, tabB,
                 kn[0], kn[1], kn[2], kn[3], kn[4], kn[5], kn[6], yy, ll);
        y[idx]  = yy;
        ld[idx] = ll;
    }
}

extern "C" void kernel_launch(void* const* d_in, const int* in_sizes, int n_in,
                              void* d_out, int out_size) {
    const float* x = (const float*)d_in[0];
    const float* p = (const float*)d_in[1];
    float* out = (float*)d_out;
    const int n = in_sizes[0];

    float* y_ptr  = out;       // out[0:N]  = y
    float* ld_ptr = out + n;   // out[N:2N] = logdet

    const int elems_per_block = 4096;            // 256 thr * 4 * float4
    const int full_blocks = n / elems_per_block; // exact tiles, no bounds checks
    if (full_blocks > 0) {
        rqs_main_kernel<<<full_blocks, 256>>>(
            p, (const float4*)x, (float4*)y_ptr, (float4*)ld_ptr);
    }
    const int done = full_blocks * elems_per_block;
    if (done < n) {
        rqs_tail_kernel<<<4, 256>>>(p, x, y_ptr, ld_ptr, done, n);
    }
}

// round 11
// speedup vs baseline: 1.1192x; 1.1192x over previous
#include <cuda_runtime.h>
#include <cstdint>
#include <math.h>

#define RANGE_MIN (-5.0f)
#define RANGE_MAX (5.0f)
#define MIN_BIN_SIZE 0.0001f
#define MIN_SLOPE 0.0001f
#define KBINS 8

// Global blob written by prep kernel (56 floats):
//  [0..31]  tabA: per bin b at 4*b: nxkw(=-x_k*inv_w), inv_w, y_k, h
//  [32..47] tabB: per bin b at 32+2*b: d_k, d_k1
//  [48..54] interior knots x_pos[1..7]
__device__ __align__(16) float g_small[56];

__global__ void rqs_prep_kernel(const float* __restrict__ p) {
    if (threadIdx.x != 0 || blockIdx.x != 0) return;

    float w[KBINS], h[KBINS], d[KBINS + 1];
    float mw = -1e30f, mh = -1e30f;
    for (int i = 0; i < KBINS; i++) {
        mw = fmaxf(mw, p[i]);
        mh = fmaxf(mh, p[KBINS + i]);
    }
    float sw = 0.f, sh = 0.f;
    for (int i = 0; i < KBINS; i++) {
        w[i] = expf(p[i] - mw);         sw += w[i];
        h[i] = expf(p[KBINS + i] - mh); sh += h[i];
    }
    const float total = RANGE_MAX - RANGE_MIN;
    const float scale = total - KBINS * MIN_BIN_SIZE;
    for (int i = 0; i < KBINS; i++) {
        w[i] = w[i] / sw * scale + MIN_BIN_SIZE;
        h[i] = h[i] / sh * scale + MIN_BIN_SIZE;
    }
    const float off = logf(expf(1.0f - MIN_SLOPE) - 1.0f);
    for (int i = 0; i <= KBINS; i++) {
        float z = p[2 * KBINS + i] + off;
        d[i] = ((z > 20.f) ? z : log1pf(expf(z))) + MIN_SLOPE;
    }
    float xp[KBINS + 1], yp[KBINS + 1];
    xp[0] = RANGE_MIN; yp[0] = RANGE_MIN;
    float cx = 0.f, cy = 0.f;
    for (int i = 0; i < KBINS; i++) {
        cx += w[i]; xp[i + 1] = RANGE_MIN + cx;
        cy += h[i]; yp[i + 1] = RANGE_MIN + cy;
    }
    for (int b = 0; b < KBINS; b++) {
        float wid   = xp[b + 1] - xp[b];
        float hei   = yp[b + 1] - yp[b];
        float inv_w = 1.0f / wid;
        g_small[b * 4 + 0] = -xp[b] * inv_w;
        g_small[b * 4 + 1] = inv_w;
        g_small[b * 4 + 2] = yp[b];
        g_small[b * 4 + 3] = hei;
        g_small[32 + b * 2 + 0] = d[b];
        g_small[32 + b * 2 + 1] = d[b + 1];
    }
    for (int i = 0; i < 7; i++) g_small[48 + i] = xp[1 + i];
    g_small[55] = 0.f;
}

__device__ __forceinline__ void rqs_eval(float xx,
                                         const float* __restrict__ tabA,
                                         const float* __restrict__ tabB,
                                         float k1, float k2, float k3, float k4,
                                         float k5, float k6, float k7,
                                         float& y_out, float& ld_out) {
    float xc = fminf(fmaxf(xx, RANGE_MIN), RANGE_MAX);

    // binary searchsorted over 7 interior knots (side='right'); oA = bin*16 bytes
    bool  c2  = xc >= k4;
    float km1 = c2 ? k6 : k2;
    bool  c1  = xc >= km1;
    float kmA = c2 ? k7 : k3;
    float kmB = c2 ? k5 : k1;
    float km0 = c1 ? kmA : kmB;
    bool  c0  = xc >= km0;
    int oA = (c2 ? 64 : 0) + (c1 ? 32 : 0) + (c0 ? 16 : 0);
    int oB = oA >> 1;

    const float4 lo = *reinterpret_cast<const float4*>((const char*)tabA + oA); // nxkw, inv_w, y_k, h
    const float2 dd = *reinterpret_cast<const float2*>((const char*)tabB + oB); // d_k, d_k1

    float xi   = fmaf(xc, lo.y, lo.x);
    float omxi = 1.0f - xi;
    float xom  = xi * omxi;

    float dk = dd.x, dk1 = dd.y;
    float s  = lo.w * lo.y;                    // h * inv_w
    float cc = fmaf(-2.0f, s, dk + dk1);       // dk + dk1 - 2s

    float num = fmaf(s * xi, xi, dk * xom);
    float den = fmaf(cc, xom, s);
    float r   = __fdividef(1.0f, den);

    float y = fmaf(lo.w * num, r, lo.z);
    // tail: below range -> d0 (= dk of bin 0), above -> d8 (= dk1 of bin 7);
    // (xx - xc) == 0 in-range, so the select value is irrelevant there.
    float edge = (xx < 0.0f) ? dk : dk1;
    y = fmaf(xx - xc, edge, y);

    float t4    = fmaf(s + s, xom, (dk * omxi) * omxi);
    float inner = fmaf(dk1 * xi, xi, t4);
    float srr   = s * r;
    ld_out = __logf(srr * srr * inner);   // == log(edge slope) at clamped bounds
    y_out  = y;
}

// 4 LDG.128 up front (MLP=4); tables broadcast-loaded from global (no serial
// per-block build); 24B smem gather per element, conflict-free banking.
__global__ void __launch_bounds__(256, 5) rqs_main_kernel(
    const float4* __restrict__ x4,
    float4* __restrict__ y4,
    float4* __restrict__ ld4
) {
    __shared__ __align__(16) float smem[56];
    if (threadIdx.x < 56) smem[threadIdx.x] = g_small[threadIdx.x];
    __syncthreads();

    const float* tabA = smem;        // 16B stride per bin
    const float* tabB = smem + 32;   // 8B stride per bin

    const float k1 = smem[48], k2 = smem[49], k3 = smem[50], k4 = smem[51];
    const float k5 = smem[52], k6 = smem[53], k7 = smem[54];

    const int tid = threadIdx.x;
    const int i0  = blockIdx.x * 1024 + tid;

    // all input loads issued up front — 4 outstanding LDG.128 per thread
    float4 xv0 = __ldcs(&x4[i0]);
    float4 xv1 = __ldcs(&x4[i0 + 256]);
    float4 xv2 = __ldcs(&x4[i0 + 512]);
    float4 xv3 = __ldcs(&x4[i0 + 768]);

    float4 yv, lv;

    rqs_eval(xv0.x, tabA, tabB, k1,k2,k3,k4,k5,k6,k7, yv.x, lv.x);
    rqs_eval(xv0.y, tabA, tabB, k1,k2,k3,k4,k5,k6,k7, yv.y, lv.y);
    rqs_eval(xv0.z, tabA, tabB, k1,k2,k3,k4,k5,k6,k7, yv.z, lv.z);
    rqs_eval(xv0.w, tabA, tabB, k1,k2,k3,k4,k5,k6,k7, yv.w, lv.w);
    __stcs(&y4[i0],  yv);
    __stcs(&ld4[i0], lv);

    rqs_eval(xv1.x, tabA, tabB, k1,k2,k3,k4,k5,k6,k7, yv.x, lv.x);
    rqs_eval(xv1.y, tabA, tabB, k1,k2,k3,k4,k5,k6,k7, yv.y, lv.y);
    rqs_eval(xv1.z, tabA, tabB, k1,k2,k3,k4,k5,k6,k7, yv.z, lv.z);
    rqs_eval(xv1.w, tabA, tabB, k1,k2,k3,k4,k5,k6,k7, yv.w, lv.w);
    __stcs(&y4[i0 + 256],  yv);
    __stcs(&ld4[i0 + 256], lv);

    rqs_eval(xv2.x, tabA, tabB, k1,k2,k3,k4,k5,k6,k7, yv.x, lv.x);
    rqs_eval(xv2.y, tabA, tabB, k1,k2,k3,k4,k5,k6,k7, yv.y, lv.y);
    rqs_eval(xv2.z, tabA, tabB, k1,k2,k3,k4,k5,k6,k7, yv.z, lv.z);
    rqs_eval(xv2.w, tabA, tabB, k1,k2,k3,k4,k5,k6,k7, yv.w, lv.w);
    __stcs(&y4[i0 + 512],  yv);
    __stcs(&ld4[i0 + 512], lv);

    rqs_eval(xv3.x, tabA, tabB, k1,k2,k3,k4,k5,k6,k7, yv.x, lv.x);
    rqs_eval(xv3.y, tabA, tabB, k1,k2,k3,k4,k5,k6,k7, yv.y, lv.y);
    rqs_eval(xv3.z, tabA, tabB, k1,k2,k3,k4,k5,k6,k7, yv.z, lv.z);
    rqs_eval(xv3.w, tabA, tabB, k1,k2,k3,k4,k5,k6,k7, yv.w, lv.w);
    __stcs(&y4[i0 + 768],  yv);
    __stcs(&ld4[i0 + 768], lv);
}

// Tail: handles [start, n) scalar-wise (not launched when n % 4096 == 0)
__global__ void rqs_tail_kernel(const float* __restrict__ x,
                                float* __restrict__ y,
                                float* __restrict__ ld,
                                int start, int n) {
    __shared__ __align__(16) float smem[56];
    if (threadIdx.x < 56) smem[threadIdx.x] = g_small[threadIdx.x];
    __syncthreads();
    for (int idx = start + blockIdx.x * blockDim.x + threadIdx.x; idx < n;
         idx += gridDim.x * blockDim.x) {
        float yy, ll;
        rqs_eval(x[idx], smem, smem + 32,
                 smem[48], smem[49], smem[50], smem[51],
                 smem[52], smem[53], smem[54], yy, ll);
        y[idx]  = yy;
        ld[idx] = ll;
    }
}

extern "C" void kernel_launch(void* const* d_in, const int* in_sizes, int n_in,
                              void* d_out, int out_size) {
    const float* x = (const float*)d_in[0];
    const float* p = (const float*)d_in[1];
    float* out = (float*)d_out;
    const int n = in_sizes[0];

    float* y_ptr  = out;       // out[0:N]  = y
    float* ld_ptr = out + n;   // out[N:2N] = logdet

    rqs_prep_kernel<<<1, 32>>>(p);

    const int elems_per_block = 4096;            // 256 thr * 4 * float4
    const int full_blocks = n / elems_per_block; // exact tiles, no bounds checks
    if (full_blocks > 0) {
        rqs_main_kernel<<<full_blocks, 256>>>(
            (const float4*)x, (float4*)y_ptr, (float4*)ld_ptr);
    }
    const int done = full_blocks * elems_per_block;
    if (done < n) {
        rqs_tail_kernel<<<4, 256>>>(x, y_ptr, ld_ptr, done, n);
    }
}

// round 12
// speedup vs baseline: 1.1744x; 1.0494x over previous
#include <cuda_runtime.h>
#include <cstdint>
#include <math.h>

#define RANGE_MIN (-5.0f)
#define RANGE_MAX (5.0f)
#define MIN_BIN_SIZE 0.0001f
#define MIN_SLOPE 0.0001f
#define KBINS 8

// Global blob (112 floats):
//  per bin b, stride 12 (48B => conflict-free dual LDS.128):
//   [b*12+0..3] = nxkw(-x_k*inv_w), inv_w, y_k, A(=h*(s-dk))
//   [b*12+4..7] = B(=h*dk), cc(=dk+dk1-2s), s, dk
//  [96..102] interior knots x_pos[1..7]
//  [103] = d0 (left edge slope), [104] = d8 (right edge slope)
__device__ __align__(16) float g_small[112];

__global__ void rqs_prep_kernel(const float* __restrict__ p) {
    if (threadIdx.x != 0 || blockIdx.x != 0) return;

    float w[KBINS], h[KBINS], d[KBINS + 1];
    float mw = -1e30f, mh = -1e30f;
    for (int i = 0; i < KBINS; i++) {
        mw = fmaxf(mw, p[i]);
        mh = fmaxf(mh, p[KBINS + i]);
    }
    float sw = 0.f, sh = 0.f;
    for (int i = 0; i < KBINS; i++) {
        w[i] = expf(p[i] - mw);         sw += w[i];
        h[i] = expf(p[KBINS + i] - mh); sh += h[i];
    }
    const float total = RANGE_MAX - RANGE_MIN;
    const float scale = total - KBINS * MIN_BIN_SIZE;
    for (int i = 0; i < KBINS; i++) {
        w[i] = w[i] / sw * scale + MIN_BIN_SIZE;
        h[i] = h[i] / sh * scale + MIN_BIN_SIZE;
    }
    const float off = logf(expf(1.0f - MIN_SLOPE) - 1.0f);
    for (int i = 0; i <= KBINS; i++) {
        float z = p[2 * KBINS + i] + off;
        d[i] = ((z > 20.f) ? z : log1pf(expf(z))) + MIN_SLOPE;
    }
    float xp[KBINS + 1], yp[KBINS + 1];
    xp[0] = RANGE_MIN; yp[0] = RANGE_MIN;
    float cx = 0.f, cy = 0.f;
    for (int i = 0; i < KBINS; i++) {
        cx += w[i]; xp[i + 1] = RANGE_MIN + cx;
        cy += h[i]; yp[i + 1] = RANGE_MIN + cy;
    }
    for (int i = 0; i < 112; i++) g_small[i] = 0.f;
    for (int b = 0; b < KBINS; b++) {
        float wid   = xp[b + 1] - xp[b];
        float hei   = yp[b + 1] - yp[b];
        float inv_w = 1.0f / wid;
        float s     = hei / wid;
        float dk    = d[b];
        float dk1   = d[b + 1];
        g_small[b * 12 + 0] = -xp[b] * inv_w;
        g_small[b * 12 + 1] = inv_w;
        g_small[b * 12 + 2] = yp[b];
        g_small[b * 12 + 3] = hei * (s - dk);       // A
        g_small[b * 12 + 4] = hei * dk;             // B
        g_small[b * 12 + 5] = dk1 + dk - 2.0f * s;  // cc
        g_small[b * 12 + 6] = s;
        g_small[b * 12 + 7] = dk;
    }
    for (int i = 0; i < 7; i++) g_small[96 + i] = xp[1 + i];
    g_small[103] = d[0];
    g_small[104] = d[KBINS];
}

__device__ __forceinline__ void rqs_eval(float xx, const float* __restrict__ stab,
                                         float k1, float k2, float k3, float k4,
                                         float k5, float k6, float k7,
                                         float d0, float d8,
                                         float& y_out, float& ld_out) {
    float xc = fminf(fmaxf(xx, RANGE_MIN), RANGE_MAX);

    // binary searchsorted over 7 interior knots (side='right'); oA = bin*48 bytes
    bool  c2  = xc >= k4;
    float km1 = c2 ? k6 : k2;
    bool  c1  = xc >= km1;
    float kmA = c2 ? k7 : k3;
    float kmB = c2 ? k5 : k1;
    float km0 = c1 ? kmA : kmB;
    bool  c0  = xc >= km0;
    int oA = (c2 ? 192 : 0) + (c1 ? 96 : 0) + (c0 ? 48 : 0);

    const float* bp = (const float*)((const char*)stab + oA);
    const float4 lo = *reinterpret_cast<const float4*>(bp);      // nxkw, inv_w, y_k, A
    const float4 hi = *reinterpret_cast<const float4*>(bp + 4);  // B, cc, s, dk

    float xi = fmaf(xc, lo.y, lo.x);

    float B = hi.x, cc = hi.y, s = hi.z, dk = hi.w;

    // y = y_k + xi*(A*xi + B) / den,  den = (-cc)*xi^2 + cc*xi + s
    float num = xi * fmaf(lo.w, xi, B);
    float den = fmaf(fmaf(-cc, xi, cc), xi, s);
    float r   = __fdividef(1.0f, den);
    float y   = fmaf(num, r, lo.z);

    // linear tail (0 in-range); edge slopes are global scalars d0/d8
    float edge = (xx < 0.0f) ? d0 : d8;
    y = fmaf(xx - xc, edge, y);

    // inner = cc*xi^2 + 2(s-dk)*xi + dk ; deriv = (s*r)^2 * inner
    float F  = s - dk;
    float inner = fmaf(fmaf(cc, xi, F + F), xi, dk);
    float srr = s * r;
    ld_out = __logf(srr * srr * inner);   // == log(d0)/log(d8) at clamped bounds
    y_out  = y;
}

// 4 LDG.128 up front (MLP=4); Horner-form spline, 32B conflict-free smem/elem.
__global__ void __launch_bounds__(256, 5) rqs_main_kernel(
    const float4* __restrict__ x4,
    float4* __restrict__ y4,
    float4* __restrict__ ld4
) {
    __shared__ __align__(16) float smem[112];
    if (threadIdx.x < 112) smem[threadIdx.x] = g_small[threadIdx.x];
    __syncthreads();

    const float k1 = smem[96],  k2 = smem[97],  k3 = smem[98],  k4 = smem[99];
    const float k5 = smem[100], k6 = smem[101], k7 = smem[102];
    const float d0 = smem[103], d8 = smem[104];

    const int tid = threadIdx.x;
    const int i0  = blockIdx.x * 1024 + tid;

    // all input loads issued up front — 4 outstanding LDG.128 per thread
    float4 xv0 = __ldcs(&x4[i0]);
    float4 xv1 = __ldcs(&x4[i0 + 256]);
    float4 xv2 = __ldcs(&x4[i0 + 512]);
    float4 xv3 = __ldcs(&x4[i0 + 768]);

    float4 yv, lv;

    rqs_eval(xv0.x, smem, k1,k2,k3,k4,k5,k6,k7, d0,d8, yv.x, lv.x);
    rqs_eval(xv0.y, smem, k1,k2,k3,k4,k5,k6,k7, d0,d8, yv.y, lv.y);
    rqs_eval(xv0.z, smem, k1,k2,k3,k4,k5,k6,k7, d0,d8, yv.z, lv.z);
    rqs_eval(xv0.w, smem, k1,k2,k3,k4,k5,k6,k7, d0,d8, yv.w, lv.w);
    __stcs(&y4[i0],  yv);
    __stcs(&ld4[i0], lv);

    rqs_eval(xv1.x, smem, k1,k2,k3,k4,k5,k6,k7, d0,d8, yv.x, lv.x);
    rqs_eval(xv1.y, smem, k1,k2,k3,k4,k5,k6,k7, d0,d8, yv.y, lv.y);
    rqs_eval(xv1.z, smem, k1,k2,k3,k4,k5,k6,k7, d0,d8, yv.z, lv.z);
    rqs_eval(xv1.w, smem, k1,k2,k3,k4,k5,k6,k7, d0,d8, yv.w, lv.w);
    __stcs(&y4[i0 + 256],  yv);
    __stcs(&ld4[i0 + 256], lv);

    rqs_eval(xv2.x, smem, k1,k2,k3,k4,k5,k6,k7, d0,d8, yv.x, lv.x);
    rqs_eval(xv2.y, smem, k1,k2,k3,k4,k5,k6,k7, d0,d8, yv.y, lv.y);
    rqs_eval(xv2.z, smem, k1,k2,k3,k4,k5,k6,k7, d0,d8, yv.z, lv.z);
    rqs_eval(xv2.w, smem, k1,k2,k3,k4,k5,k6,k7, d0,d8, yv.w, lv.w);
    __stcs(&y4[i0 + 512],  yv);
    __stcs(&ld4[i0 + 512], lv);

    rqs_eval(xv3.x, smem, k1,k2,k3,k4,k5,k6,k7, d0,d8, yv.x, lv.x);
    rqs_eval(xv3.y, smem, k1,k2,k3,k4,k5,k6,k7, d0,d8, yv.y, lv.y);
    rqs_eval(xv3.z, smem, k1,k2,k3,k4,k5,k6,k7, d0,d8, yv.z, lv.z);
    rqs_eval(xv3.w, smem, k1,k2,k3,k4,k5,k6,k7, d0,d8, yv.w, lv.w);
    __stcs(&y4[i0 + 768],  yv);
    __stcs(&ld4[i0 + 768], lv);
}

// Tail: handles [start, n) scalar-wise (not launched when n % 4096 == 0)
__global__ void rqs_tail_kernel(const float* __restrict__ x,
                                float* __restrict__ y,
                                float* __restrict__ ld,
                                int start, int n) {
    __shared__ __align__(16) float smem[112];
    if (threadIdx.x < 112) smem[threadIdx.x] = g_small[threadIdx.x];
    __syncthreads();
    for (int idx = start + blockIdx.x * blockDim.x + threadIdx.x; idx < n;
         idx += gridDim.x * blockDim.x) {
        float yy, ll;
        rqs_eval(x[idx], smem,
                 smem[96], smem[97], smem[98], smem[99],
                 smem[100], smem[101], smem[102],
                 smem[103], smem[104], yy, ll);
        y[idx]  = yy;
        ld[idx] = ll;
    }
}

extern "C" void kernel_launch(void* const* d_in, const int* in_sizes, int n_in,
                              void* d_out, int out_size) {
    const float* x = (const float*)d_in[0];
    const float* p = (const float*)d_in[1];
    float* out = (float*)d_out;
    const int n = in_sizes[0];

    float* y_ptr  = out;       // out[0:N]  = y
    float* ld_ptr = out + n;   // out[N:2N] = logdet

    rqs_prep_kernel<<<1, 32>>>(p);

    const int elems_per_block = 4096;            // 256 thr * 4 * float4
    const int full_blocks = n / elems_per_block; // exact tiles, no bounds checks
    if (full_blocks > 0) {
        rqs_main_kernel<<<full_blocks, 256>>>(
            (const float4*)x, (float4*)y_ptr, (float4*)ld_ptr);
    }
    const int done = full_blocks * elems_per_block;
    if (done < n) {
        rqs_tail_kernel<<<4, 256>>>(x, y_ptr, ld_ptr, done, n);
    }
}

// round 13
// speedup vs baseline: 1.1844x; 1.0085x over previous
#include <cuda_runtime.h>
#include <cstdint>
#include <math.h>

#define RANGE_MIN (-5.0f)
#define RANGE_MAX (5.0f)
#define MIN_BIN_SIZE 0.0001f
#define MIN_SLOPE 0.0001f
#define KBINS 8

// Global blob (112 floats):
//  per bin b, stride 12 (48B => conflict-free dual LDS.128):
//   [b*12+0..3] = nxkw(-x_k*inv_w), inv_w, y_k, A(=h*(s-dk))
//   [b*12+4..7] = B(=h*dk), cc(=dk+dk1-2s), s, dk
//  [96..102] interior knots x_pos[1..7]
//  [103] = d0 (left edge slope), [104] = d8 (right edge slope)
__device__ __align__(16) float g_small[112];

// Parallel prep: lanes 0-7 width exps, 8-15 height exps, 16-24 softplus slopes;
// lane 0 finishes with the cheap serial algebra (sums/cumsums/table writes).
__global__ void rqs_prep_kernel(const float* __restrict__ p) {
    __shared__ float sp[25];
    __shared__ float se[25];   // exps / softplus results
    const int t = threadIdx.x;

    if (t < 25) sp[t] = p[t];
    __syncwarp();

    if (t < 8) {
        float mw = sp[0];
        #pragma unroll
        for (int i = 1; i < 8; i++) mw = fmaxf(mw, sp[i]);
        se[t] = __expf(sp[t] - mw);
    } else if (t < 16) {
        float mh = sp[8];
        #pragma unroll
        for (int i = 9; i < 16; i++) mh = fmaxf(mh, sp[i]);
        se[t] = __expf(sp[t] - mh);
    } else if (t < 25) {
        // softplus(p + off) + MIN_SLOPE, off = log(exp(1-MIN_SLOPE)-1)
        const float off = 0.54130250f;  // logf(expf(1.0f - 1e-4f) - 1.0f)
        float z = sp[t] + off;
        se[t] = __logf(1.0f + __expf(z)) + MIN_SLOPE;
    }
    __syncwarp();

    if (t == 0) {
        float sw = 0.f, sh = 0.f;
        #pragma unroll
        for (int i = 0; i < 8; i++) { sw += se[i]; sh += se[8 + i]; }
        const float total = RANGE_MAX - RANGE_MIN;
        const float scale = total - KBINS * MIN_BIN_SIZE;
        float isw = scale / sw, ish = scale / sh;

        float xp[KBINS + 1], yp[KBINS + 1];
        xp[0] = RANGE_MIN; yp[0] = RANGE_MIN;
        float cx = 0.f, cy = 0.f;
        #pragma unroll
        for (int i = 0; i < 8; i++) {
            cx += se[i]     * isw + MIN_BIN_SIZE; xp[i + 1] = RANGE_MIN + cx;
            cy += se[8 + i] * ish + MIN_BIN_SIZE; yp[i + 1] = RANGE_MIN + cy;
        }
        #pragma unroll
        for (int b = 0; b < KBINS; b++) {
            float wid   = xp[b + 1] - xp[b];
            float hei   = yp[b + 1] - yp[b];
            float inv_w = 1.0f / wid;
            float s     = hei * inv_w;
            float dk    = se[16 + b];
            float dk1   = se[17 + b];
            g_small[b * 12 + 0]  = -xp[b] * inv_w;
            g_small[b * 12 + 1]  = inv_w;
            g_small[b * 12 + 2]  = yp[b];
            g_small[b * 12 + 3]  = hei * (s - dk);       // A
            g_small[b * 12 + 4]  = hei * dk;             // B
            g_small[b * 12 + 5]  = dk1 + dk - 2.0f * s;  // cc
            g_small[b * 12 + 6]  = s;
            g_small[b * 12 + 7]  = dk;
            g_small[b * 12 + 8]  = 0.f;
            g_small[b * 12 + 9]  = 0.f;
            g_small[b * 12 + 10] = 0.f;
            g_small[b * 12 + 11] = 0.f;
        }
        #pragma unroll
        for (int i = 0; i < 7; i++) g_small[96 + i] = xp[1 + i];
        g_small[103] = se[16];
        g_small[104] = se[24];
        g_small[105] = 0.f; g_small[106] = 0.f; g_small[107] = 0.f;
        g_small[108] = 0.f; g_small[109] = 0.f; g_small[110] = 0.f;
        g_small[111] = 0.f;
    }
}

__device__ __forceinline__ void rqs_eval(float xx, const float* __restrict__ stab,
                                         float k1, float k2, float k3, float k4,
                                         float k5, float k6, float k7,
                                         float d0, float d8,
                                         float& y_out, float& ld_out) {
    float xc = fminf(fmaxf(xx, RANGE_MIN), RANGE_MAX);

    // binary searchsorted over 7 interior knots (side='right'); oA = bin*48 bytes
    bool  c2  = xc >= k4;
    float km1 = c2 ? k6 : k2;
    bool  c1  = xc >= km1;
    float kmA = c2 ? k7 : k3;
    float kmB = c2 ? k5 : k1;
    float km0 = c1 ? kmA : kmB;
    bool  c0  = xc >= km0;
    int oA = (c2 ? 192 : 0) + (c1 ? 96 : 0) + (c0 ? 48 : 0);

    const float* bp = (const float*)((const char*)stab + oA);
    const float4 lo = *reinterpret_cast<const float4*>(bp);      // nxkw, inv_w, y_k, A
    const float4 hi = *reinterpret_cast<const float4*>(bp + 4);  // B, cc, s, dk

    float xi = fmaf(xc, lo.y, lo.x);

    float B = hi.x, cc = hi.y, s = hi.z, dk = hi.w;

    // y = y_k + xi*(A*xi + B) / den,  den = (-cc)*xi^2 + cc*xi + s
    float num = xi * fmaf(lo.w, xi, B);
    float den = fmaf(fmaf(-cc, xi, cc), xi, s);
    float r   = __fdividef(1.0f, den);
    float y   = fmaf(num, r, lo.z);

    // linear tail (0 in-range); edge slopes are global scalars d0/d8
    float edge = (xx < 0.0f) ? d0 : d8;
    y = fmaf(xx - xc, edge, y);

    // inner = cc*xi^2 + 2(s-dk)*xi + dk ; deriv = (s*r)^2 * inner
    float F  = s - dk;
    float inner = fmaf(fmaf(cc, xi, F + F), xi, dk);
    float srr = s * r;
    ld_out = __logf(srr * srr * inner);   // == log(d0)/log(d8) at clamped bounds
    y_out  = y;
}

// 4 LDG.128 up front (MLP=4); Horner-form spline, 32B conflict-free smem/elem.
__global__ void __launch_bounds__(256, 5) rqs_main_kernel(
    const float4* __restrict__ x4,
    float4* __restrict__ y4,
    float4* __restrict__ ld4
) {
    __shared__ __align__(16) float smem[112];
    if (threadIdx.x < 112) smem[threadIdx.x] = g_small[threadIdx.x];
    __syncthreads();

    const float k1 = smem[96],  k2 = smem[97],  k3 = smem[98],  k4 = smem[99];
    const float k5 = smem[100], k6 = smem[101], k7 = smem[102];
    const float d0 = smem[103], d8 = smem[104];

    const int tid = threadIdx.x;
    const int i0  = blockIdx.x * 1024 + tid;

    // all input loads issued up front — 4 outstanding LDG.128 per thread
    float4 xv0 = __ldcs(&x4[i0]);
    float4 xv1 = __ldcs(&x4[i0 + 256]);
    float4 xv2 = __ldcs(&x4[i0 + 512]);
    float4 xv3 = __ldcs(&x4[i0 + 768]);

    float4 yv, lv;

    rqs_eval(xv0.x, smem, k1,k2,k3,k4,k5,k6,k7, d0,d8, yv.x, lv.x);
    rqs_eval(xv0.y, smem, k1,k2,k3,k4,k5,k6,k7, d0,d8, yv.y, lv.y);
    rqs_eval(xv0.z, smem, k1,k2,k3,k4,k5,k6,k7, d0,d8, yv.z, lv.z);
    rqs_eval(xv0.w, smem, k1,k2,k3,k4,k5,k6,k7, d0,d8, yv.w, lv.w);
    __stcs(&y4[i0],  yv);
    __stcs(&ld4[i0], lv);

    rqs_eval(xv1.x, smem, k1,k2,k3,k4,k5,k6,k7, d0,d8, yv.x, lv.x);
    rqs_eval(xv1.y, smem, k1,k2,k3,k4,k5,k6,k7, d0,d8, yv.y, lv.y);
    rqs_eval(xv1.z, smem, k1,k2,k3,k4,k5,k6,k7, d0,d8, yv.z, lv.z);
    rqs_eval(xv1.w, smem, k1,k2,k3,k4,k5,k6,k7, d0,d8, yv.w, lv.w);
    __stcs(&y4[i0 + 256],  yv);
    __stcs(&ld4[i0 + 256], lv);

    rqs_eval(xv2.x, smem, k1,k2,k3,k4,k5,k6,k7, d0,d8, yv.x, lv.x);
    rqs_eval(xv2.y, smem, k1,k2,k3,k4,k5,k6,k7, d0,d8, yv.y, lv.y);
    rqs_eval(xv2.z, smem, k1,k2,k3,k4,k5,k6,k7, d0,d8, yv.z, lv.z);
    rqs_eval(xv2.w, smem, k1,k2,k3,k4,k5,k6,k7, d0,d8, yv.w, lv.w);
    __stcs(&y4[i0 + 512],  yv);
    __stcs(&ld4[i0 + 512], lv);

    rqs_eval(xv3.x, smem, k1,k2,k3,k4,k5,k6,k7, d0,d8, yv.x, lv.x);
    rqs_eval(xv3.y, smem, k1,k2,k3,k4,k5,k6,k7, d0,d8, yv.y, lv.y);
    rqs_eval(xv3.z, smem, k1,k2,k3,k4,k5,k6,k7, d0,d8, yv.z, lv.z);
    rqs_eval(xv3.w, smem, k1,k2,k3,k4,k5,k6,k7, d0,d8, yv.w, lv.w);
    __stcs(&y4[i0 + 768],  yv);
    __stcs(&ld4[i0 + 768], lv);
}

// Tail: handles [start, n) scalar-wise (not launched when n % 4096 == 0)
__global__ void rqs_tail_kernel(const float* __restrict__ x,
                                float* __restrict__ y,
                                float* __restrict__ ld,
                                int start, int n) {
    __shared__ __align__(16) float smem[112];
    if (threadIdx.x < 112) smem[threadIdx.x] = g_small[threadIdx.x];
    __syncthreads();
    for (int idx = start + blockIdx.x * blockDim.x + threadIdx.x; idx < n;
         idx += gridDim.x * blockDim.x) {
        float yy, ll;
        rqs_eval(x[idx], smem,
                 smem[96], smem[97], smem[98], smem[99],
                 smem[100], smem[101], smem[102],
                 smem[103], smem[104], yy, ll);
        y[idx]  = yy;
        ld[idx] = ll;
    }
}

extern "C" void kernel_launch(void* const* d_in, const int* in_sizes, int n_in,
                              void* d_out, int out_size) {
    const float* x = (const float*)d_in[0];
    const float* p = (const float*)d_in[1];
    float* out = (float*)d_out;
    const int n = in_sizes[0];

    float* y_ptr  = out;       // out[0:N]  = y
    float* ld_ptr = out + n;   // out[N:2N] = logdet

    rqs_prep_kernel<<<1, 32>>>(p);

    const int elems_per_block = 4096;            // 256 thr * 4 * float4
    const int full_blocks = n / elems_per_block; // exact tiles, no bounds checks
    if (full_blocks > 0) {
        rqs_main_kernel<<<full_blocks, 256>>>(
            (const float4*)x, (float4*)y_ptr, (float4*)ld_ptr);
    }
    const int done = full_blocks * elems_per_block;
    if (done < n) {
        rqs_tail_kernel<<<4, 256>>>(x, y_ptr, ld_ptr, done, n);
    }
}